// round 5
// baseline (speedup 1.0000x reference)
#include <cuda_runtime.h>

// ----------------------------------------------------------------------------
// Tropical (max-plus) ViT, fp32.  C[m,n] = max_k (A[m,k]+B[n,k]) everywhere.
// Round 4: K<=64 per block (split-K 2..4 on all GEMMs, combines folded into
// loaders / follower kernels), both k-tiles loaded up-front, ONE barrier per
// kernel, grids 784-1176 blocks.
// ----------------------------------------------------------------------------

#define NEG_INF (-3.0e38f)
#define BB     8
#define NPATCH 196
#define DD     128
#define DFF    256
#define NPAD   224
#define MTOT   1568
#define NCLS   1000

__device__ float g_h   [MTOT * DD];
__device__ float g_xn  [MTOT * DD];
__device__ float g_q   [2][MTOT * DD];
__device__ float g_k   [2][MTOT * DD];
__device__ float g_vT  [2][BB * DD * NPAD];      // [b][d][j], j-pads stay 0
__device__ float g_s   [2][BB * NPATCH * NPAD];  // [b][i][j], j-pads = -inf
__device__ float g_a   [4][MTOT * DD];
__device__ float g_h1  [2][MTOT * DFF];
__device__ float g_pool[BB * DD];

enum { M_EMBED, M_QKV, M_SCORES, M_ATT, M_FF1, M_FF2 };

__device__ __forceinline__ float4 f4max(float4 a, float4 b) {
    a.x = fmaxf(a.x, b.x); a.y = fmaxf(a.y, b.y);
    a.z = fmaxf(a.z, b.z); a.w = fmaxf(a.w, b.w);
    return a;
}

// ---------------------------------------------------------------------------
// Tropical NT GEMM: 32x32 tile, 128 threads, 2x4 per thread, K<=64 per block.
// A,B row stride == K. Dual-source loaders (max-combine) per MODE.
// ---------------------------------------------------------------------------
template<int MODE>
__global__ __launch_bounds__(128) void tg(
    const float* __restrict__ A, const float* __restrict__ A2,
    const float* __restrict__ B, const float* __restrict__ B2,
    const float* __restrict__ B3,
    float* __restrict__ C0, float* __restrict__ C1,
    float* __restrict__ C2, float* __restrict__ C3,
    int M, int N, int K, int ldc,
    int aBatch, int bBatch, int cBatch,
    int splitShift, const float* __restrict__ aux)
{
    __shared__ __align__(16) float As[2][32][34];
    __shared__ __align__(16) float Bs[2][32][36];

    const int t  = threadIdx.x;
    const int tx = t & 7;            // n group (4 cols)
    const int ty = t >> 3;           // m group (2 rows)
    const int lk = tx << 2;
    const int lr = ty;
    const int bm = blockIdx.y << 5;
    const int bn = blockIdx.x << 5;

    const int z      = blockIdx.z;
    const int half   = z & ((1 << splitShift) - 1);
    const int batch  = z >> splitShift;
    const int kBegin = half << 6;                 // 64 per split
    const int kEnd   = min(K, kBegin + 64);
    const int nst    = (kEnd - kBegin + 31) >> 5; // 1 or 2 k-tiles

    const bool dualA = (MODE == M_SCORES || MODE == M_ATT || MODE == M_FF2);
    const bool dualB = (MODE == M_SCORES || MODE == M_ATT);
    const long dA = dualA ? (A2 - A) : 0;
    const long dB = dualB ? (B2 - B) : 0;
    const float tauv = (MODE == M_FF2) ? aux[0] : 0.f;

    const float* Ab = A + (long)batch * aBatch;
    const float* Bb = B + (long)batch * bBatch;

    const float* arow[2];
#pragma unroll
    for (int h = 0; h < 2; ++h) {
        int ra = bm + lr + 16 * h; if (ra > M - 1) ra = M - 1;
        if (MODE == M_EMBED) {
            int b = ra / NPATCH, np = ra % NPATCH;
            arow[h] = A + ((long)(b * 224 + (np / 14) * 16)) * 224 + (np % 14) * 16;
        } else {
            arow[h] = Ab + (long)ra * K;
        }
    }
    const float* brow[2];
#pragma unroll
    for (int h = 0; h < 2; ++h) {
        int rb = bn + lr + 16 * h; if (rb > N - 1) rb = N - 1;
        if (MODE == M_QKV) {
            const float* Bp = rb < 128 ? B : (rb < 256 ? B2 : B3);
            brow[h] = Bp + (long)(rb & 127) * K;
        } else {
            brow[h] = Bb + (long)rb * K;
        }
    }

    // ---- load ALL k-tiles up-front (MLP), single barrier ----
    float4 la[2][2], lb[2][2];
#pragma unroll
    for (int st = 0; st < 2; ++st) {
        if (st >= nst) break;
        const int kk = kBegin + (st << 5);
#pragma unroll
        for (int h = 0; h < 2; ++h) {
            float4 va;
            if (MODE == M_EMBED) {
                int j = kk + lk;
                va = *(const float4*)(arow[h] + (j >> 4) * 224 + (j & 15));
            } else {
                va = *(const float4*)(arow[h] + kk + lk);
                if (dualA)
                    va = f4max(va, *(const float4*)(arow[h] + dA + kk + lk));
                if (MODE == M_FF2) {
                    va.x = fmaxf(va.x, tauv); va.y = fmaxf(va.y, tauv);
                    va.z = fmaxf(va.z, tauv); va.w = fmaxf(va.w, tauv);
                }
            }
            la[st][h] = va;
            float4 vb = *(const float4*)(brow[h] + kk + lk);
            if (dualB)
                vb = f4max(vb, *(const float4*)(brow[h] + dB + kk + lk));
            lb[st][h] = vb;
        }
    }
#pragma unroll
    for (int st = 0; st < 2; ++st) {
        if (st >= nst) break;
#pragma unroll
        for (int h = 0; h < 2; ++h) {
            int r = lr + 16 * h;
            As[st][lk + 0][r] = la[st][h].x;
            As[st][lk + 1][r] = la[st][h].y;
            As[st][lk + 2][r] = la[st][h].z;
            As[st][lk + 3][r] = la[st][h].w;
            Bs[st][lk + 0][r] = lb[st][h].x;
            Bs[st][lk + 1][r] = lb[st][h].y;
            Bs[st][lk + 2][r] = lb[st][h].z;
            Bs[st][lk + 3][r] = lb[st][h].w;
        }
    }
    __syncthreads();

    // ---- compute: straight run, no further barriers ----
    float acc[2][4];
#pragma unroll
    for (int i = 0; i < 2; ++i)
#pragma unroll
        for (int j = 0; j < 4; ++j) acc[i][j] = NEG_INF;

#pragma unroll
    for (int st = 0; st < 2; ++st) {
        if (st >= nst) break;
#pragma unroll
        for (int k = 0; k < 32; ++k) {
            float2 av = *(const float2*)&As[st][k][ty * 2];
            float4 bv = *(const float4*)&Bs[st][k][tx * 4];
            acc[0][0] = fmaxf(acc[0][0], av.x + bv.x);
            acc[0][1] = fmaxf(acc[0][1], av.x + bv.y);
            acc[0][2] = fmaxf(acc[0][2], av.x + bv.z);
            acc[0][3] = fmaxf(acc[0][3], av.x + bv.w);
            acc[1][0] = fmaxf(acc[1][0], av.y + bv.x);
            acc[1][1] = fmaxf(acc[1][1], av.y + bv.y);
            acc[1][2] = fmaxf(acc[1][2], av.y + bv.z);
            acc[1][3] = fmaxf(acc[1][3], av.y + bv.w);
        }
    }

    // ---- epilogue ----
    float* Cs4[4] = { C0, C1, C2, C3 };
    float* Ch = Cs4[half] + (long)batch * cBatch;
#pragma unroll
    for (int i = 0; i < 2; ++i) {
        int m = bm + ty * 2 + i;
        if (m >= M) continue;
#pragma unroll
        for (int j = 0; j < 4; ++j) {
            int n = bn + tx * 4 + j;
            float v = acc[i][j];
            if (MODE == M_QKV) {
                if (n < DD)
                    (C0 + (long)half * (MTOT * DD))[(long)m * DD + n] = v;
                else if (n < 2 * DD)
                    (C1 + (long)half * (MTOT * DD))[(long)m * DD + (n - DD)] = v;
                else {
                    int b = m / NPATCH, ii = m % NPATCH;
                    (C2 + (long)half * (BB * DD * NPAD))
                        [((long)b * DD + (n - 2 * DD)) * NPAD + ii] = v;
                }
            } else if (MODE == M_SCORES) {
                Ch[(long)m * ldc + n] = (n < N) ? v : NEG_INF;
            } else {
                Ch[(long)m * ldc + n] = v;
            }
        }
    }
}

// h = max4(a)+pos;  xn = h - rowmax(h)
__global__ void pnorm4_k(const float* __restrict__ a0, const float* __restrict__ a1,
                         const float* __restrict__ a2, const float* __restrict__ a3,
                         const float* __restrict__ pos,
                         float* __restrict__ h, float* __restrict__ xn)
{
    __shared__ float s[4];
    int r = blockIdx.x, t = threadIdx.x;
    long idx = (long)r * DD + t;
    float v = fmaxf(fmaxf(a0[idx], a1[idx]), fmaxf(a2[idx], a3[idx]))
            + pos[(r % NPATCH) * DD + t];
    float m = v;
#pragma unroll
    for (int o = 16; o; o >>= 1) m = fmaxf(m, __shfl_xor_sync(0xffffffffu, m, o));
    if ((t & 31) == 0) s[t >> 5] = m;
    __syncthreads();
    m = fmaxf(fmaxf(s[0], s[1]), fmaxf(s[2], s[3]));
    h[idx] = v;
    xn[idx] = v - m;
}

// av = max4(a); h = max(h, av - rowmax(av)); xn = h - rowmax(h)
__global__ void residual4_k(const float* __restrict__ a0, const float* __restrict__ a1,
                            const float* __restrict__ a2, const float* __restrict__ a3,
                            float* __restrict__ h, float* __restrict__ xn)
{
    __shared__ float s[4];
    int r = blockIdx.x, t = threadIdx.x;
    long idx = (long)r * DD + t;
    float av = fmaxf(fmaxf(a0[idx], a1[idx]), fmaxf(a2[idx], a3[idx]));
    float m = av;
#pragma unroll
    for (int o = 16; o; o >>= 1) m = fmaxf(m, __shfl_xor_sync(0xffffffffu, m, o));
    if ((t & 31) == 0) s[t >> 5] = m;
    __syncthreads();
    m = fmaxf(fmaxf(s[0], s[1]), fmaxf(s[2], s[3]));
    float hv = fmaxf(h[idx], av - m);
    h[idx] = hv;
    __syncthreads();
    float m2 = hv;
#pragma unroll
    for (int o = 16; o; o >>= 1) m2 = fmaxf(m2, __shfl_xor_sync(0xffffffffu, m2, o));
    if ((t & 31) == 0) s[t >> 5] = m2;
    __syncthreads();
    m2 = fmaxf(fmaxf(s[0], s[1]), fmaxf(s[2], s[3]));
    xn[idx] = hv - m2;
}

__global__ void pool_k()
{
    int b = blockIdx.x, t = threadIdx.x;
    float acc = NEG_INF;
    const float* base = g_h + (long)b * NPATCH * DD + t;
#pragma unroll 4
    for (int n = 0; n < NPATCH; ++n) acc = fmaxf(acc, base[(long)n * DD]);
    g_pool[b * DD + t] = acc;
}

__global__ void head_k(const float* __restrict__ W, const float* __restrict__ ls,
                       float* __restrict__ out)
{
    __shared__ float p[DD];
    int b = blockIdx.y, t = threadIdx.x;
    p[t] = g_pool[b * DD + t];
    __syncthreads();
    int c = blockIdx.x * 128 + t;
    if (c < NCLS) {
        float acc = NEG_INF;
        const float* w = W + (long)c * DD;
#pragma unroll 4
        for (int d = 0; d < DD; ++d) acc = fmaxf(acc, p[d] + w[d]);
        out[(long)b * NCLS + c] = acc * ls[0];
    }
}

// ---------------------------------------------------------------------------

extern "C" void kernel_launch(void* const* d_in, const int* in_sizes, int n_in,
                              void* d_out, int out_size)
{
    (void)in_sizes; (void)n_in; (void)out_size;
    const float* x       = (const float*)d_in[0];
    const float* embed_W = (const float*)d_in[1];
    const float* pos     = (const float*)d_in[2];
    const float* head_W  = (const float*)d_in[15];
    const float* lscale  = (const float*)d_in[16];
    float* out = (float*)d_out;

    float *h, *xn, *q, *k, *vT, *s, *a, *h1;
    cudaGetSymbolAddress((void**)&h,  g_h);
    cudaGetSymbolAddress((void**)&xn, g_xn);
    cudaGetSymbolAddress((void**)&q,  g_q);
    cudaGetSymbolAddress((void**)&k,  g_k);
    cudaGetSymbolAddress((void**)&vT, g_vT);
    cudaGetSymbolAddress((void**)&s,  g_s);
    cudaGetSymbolAddress((void**)&a,  g_a);
    cudaGetSymbolAddress((void**)&h1, g_h1);

    float *q1 = q + MTOT * DD, *k1 = k + MTOT * DD;
    float *vT1 = vT + BB * DD * NPAD, *s1 = s + BB * NPATCH * NPAD;
    float *a1 = a + MTOT * DD, *a2 = a + 2 * MTOT * DD, *a3 = a + 3 * MTOT * DD;
    float *h11 = h1 + MTOT * DFF;

    // embed (patchify fused), K=256 split4 -> a0..a3 ; combine+pos in pnorm4
    tg<M_EMBED><<<dim3(4, 49, 4), 128>>>(x, 0, embed_W, 0, 0, a, a1, a2, a3,
        MTOT, DD, 256, DD, 0, 0, 0, 2, 0);
    pnorm4_k<<<MTOT, 128>>>(a, a1, a2, a3, pos, h, xn);

    for (int l = 0; l < 2; ++l) {
        const float* qW  = (const float*)d_in[3 + 6 * l];
        const float* kW  = (const float*)d_in[4 + 6 * l];
        const float* vW  = (const float*)d_in[5 + 6 * l];
        const float* f1W = (const float*)d_in[6 + 6 * l];
        const float* f2W = (const float*)d_in[7 + 6 * l];
        const float* tau = (const float*)d_in[8 + 6 * l];

        // fused q/k/v: N=384, K=128 split2 -> {q,k,vT}[half]
        tg<M_QKV><<<dim3(12, 49, 2), 128>>>(xn, 0, qW, kW, vW, q, k, vT, 0,
            MTOT, 384, DD, 0, 0, 0, 0, 1, 0);

        // scores: A=max(q0,q1), B=max(k0,k1); K=128 split2 -> s0/s1
        tg<M_SCORES><<<dim3(7, 7, 16), 128>>>(q, q1, k, k1, 0, s, s1, 0, 0,
            NPATCH, NPATCH, DD, NPAD,
            NPATCH * DD, NPATCH * DD, NPATCH * NPAD, 1, 0);

        // attn out: A=max(s0,s1), B=max(vT0,vT1); K=224 split4 -> a0..a3
        tg<M_ATT><<<dim3(4, 7, 32), 128>>>(s, s1, vT, vT1, 0, a, a1, a2, a3,
            NPATCH, DD, NPAD, DD,
            NPATCH * NPAD, DD * NPAD, NPATCH * DD, 2, 0);
        residual4_k<<<MTOT, 128>>>(a, a1, a2, a3, h, xn);

        // ff1: K=128 split2 -> h1[half]   (tau folded into ff2 loader)
        tg<M_FF1><<<dim3(8, 49, 2), 128>>>(xn, 0, f1W, 0, 0, h1, h11, 0, 0,
            MTOT, DFF, DD, DFF, 0, 0, 0, 1, 0);

        // ff2: A=max(h1_0,h1_1,tau); K=256 split4 -> a0..a3
        tg<M_FF2><<<dim3(4, 49, 4), 128>>>(h1, h11, f2W, 0, 0, a, a1, a2, a3,
            MTOT, DD, DFF, DD, 0, 0, 0, 2, tau);
        residual4_k<<<MTOT, 128>>>(a, a1, a2, a3, h, xn);
    }

    pool_k<<<BB, 128>>>();
    head_k<<<dim3(8, BB), 128>>>(head_W, lscale, out);
}